// round 7
// baseline (speedup 1.0000x reference)
#include <cuda_runtime.h>
#include <cuda_bf16.h>
#include <math.h>
#include <stdint.h>

// Problem constants
#define B_   256
#define S_   128
#define P_   100
#define N_   500
#define E_   256
#define H_   4
#define HD_  64
#define L_   2
#define F_   1024
#define T_   (B_ * S_)      // 32768 tokens
#define NT_  (P_ + N_)      // 600 targets

// ---------------------------------------------------------------------------
// Scratch (device globals — no allocation allowed)
// ---------------------------------------------------------------------------
__device__ float g_x   [(size_t)T_ * E_];
__device__ float g_qkv [(size_t)T_ * 3 * E_];
__device__ float g_attn[(size_t)T_ * E_];
__device__ float g_ff  [(size_t)T_ * F_];
__device__ float g_out [(size_t)B_ * 3 * E_];

// ---------------------------------------------------------------------------
// cp.async helpers
// ---------------------------------------------------------------------------
__device__ __forceinline__ void cp16(void* sdst, const void* gsrc) {
    uint32_t s = (uint32_t)__cvta_generic_to_shared(sdst);
    asm volatile("cp.async.cg.shared.global [%0], [%1], 16;\n" :: "r"(s), "l"(gsrc));
}
__device__ __forceinline__ void cp_commit() {
    asm volatile("cp.async.commit_group;\n");
}
template<int NWait>
__device__ __forceinline__ void cp_wait() {
    asm volatile("cp.async.wait_group %0;\n" :: "n"(NWait));
}

__device__ __forceinline__ uint32_t f2tf32(float x) {
    uint32_t r;
    asm("cvt.rna.tf32.f32 %0, %1;" : "=r"(r) : "f"(x));
    return r;
}

#define MMA_TF32(d, a, b)                                                     \
    asm volatile(                                                             \
        "mma.sync.aligned.m16n8k8.row.col.f32.tf32.tf32.f32 "                 \
        "{%0,%1,%2,%3}, {%4,%5,%6,%7}, {%8,%9}, {%0,%1,%2,%3};"               \
        : "+f"(d[0]), "+f"(d[1]), "+f"(d[2]), "+f"(d[3])                      \
        : "r"(a[0]), "r"(a[1]), "r"(a[2]), "r"(a[3]), "r"(b[0]), "r"(b[1]))

// ---------------------------------------------------------------------------
// Embedding gather (float4)
// ---------------------------------------------------------------------------
__global__ void gather_kernel(const int* __restrict__ attr,
                              const float* __restrict__ emb,
                              float* __restrict__ x) {
    int i4 = blockIdx.x * blockDim.x + threadIdx.x;
    if (i4 < T_ * (E_ / 4)) {
        int t = i4 >> 6;
        int e4 = i4 & 63;
        ((float4*)x)[i4] = ((const float4*)emb)[(size_t)attr[t] * (E_ / 4) + e4];
    }
}

// ---------------------------------------------------------------------------
// TF32 GEMM (plain): C = A @ B^T + bias (opt ReLU). Block 128x128, BK=16,
// 8 warps of 64x32, 3-stage cp.async, 2 CTAs/SM. Used for QKV + FF1.
// ---------------------------------------------------------------------------
#define LDA    20
#define TSZ    (128 * LDA)
#define STAGES 3

template<bool RELU>
__global__ __launch_bounds__(256, 2)
void tgemm(const float* __restrict__ A, const float* __restrict__ Bm,
           const float* __restrict__ bias, float* __restrict__ C,
           int M, int N, int K) {
    extern __shared__ float smw[];
    float* As = smw;
    float* Bs = smw + STAGES * TSZ;

    const int bm   = blockIdx.y * 128;
    const int bn   = blockIdx.x * 128;
    const int t    = threadIdx.x;
    const int lane = t & 31;
    const int wid  = t >> 5;
    const int wm   = (wid & 1) * 64;
    const int wn   = (wid >> 1) * 32;
    const int g    = lane >> 2;
    const int tg   = lane & 3;

    const int lrow = t >> 1;
    const int lkb  = (t & 1) * 8;
    const float* Ap = A  + (size_t)(bm + lrow) * K + lkb;
    const float* Bp = Bm + (size_t)(bn + lrow) * K + lkb;

    float acc[4][4][4];
#pragma unroll
    for (int i = 0; i < 4; i++)
#pragma unroll
        for (int j = 0; j < 4; j++)
#pragma unroll
            for (int r = 0; r < 4; r++) acc[i][j][r] = 0.f;

    const int nk = K >> 4;
#pragma unroll
    for (int s = 0; s < STAGES - 1; s++) {
        const int k0 = s << 4;
        cp16(&As[s * TSZ + lrow * LDA + lkb],     Ap + k0);
        cp16(&As[s * TSZ + lrow * LDA + lkb + 4], Ap + k0 + 4);
        cp16(&Bs[s * TSZ + lrow * LDA + lkb],     Bp + k0);
        cp16(&Bs[s * TSZ + lrow * LDA + lkb + 4], Bp + k0 + 4);
        cp_commit();
    }

    int cur = 0;
    for (int kt = 0; kt < nk; kt++) {
        if (kt < nk - 1) cp_wait<STAGES - 2>(); else cp_wait<0>();
        __syncthreads();

        const float* Ac = As + cur * TSZ;
        const float* Bc = Bs + cur * TSZ;
#pragma unroll
        for (int ks = 0; ks < 2; ks++) {
            const int k0 = ks * 8;
            uint32_t af[4][4], bf[4][2];
#pragma unroll
            for (int mf = 0; mf < 4; mf++) {
                const int row = wm + mf * 16 + g;
                af[mf][0] = f2tf32(Ac[row * LDA + k0 + tg]);
                af[mf][1] = f2tf32(Ac[(row + 8) * LDA + k0 + tg]);
                af[mf][2] = f2tf32(Ac[row * LDA + k0 + tg + 4]);
                af[mf][3] = f2tf32(Ac[(row + 8) * LDA + k0 + tg + 4]);
            }
#pragma unroll
            for (int nf = 0; nf < 4; nf++) {
                const int col = wn + nf * 8 + g;
                bf[nf][0] = f2tf32(Bc[col * LDA + k0 + tg]);
                bf[nf][1] = f2tf32(Bc[col * LDA + k0 + tg + 4]);
            }
#pragma unroll
            for (int mf = 0; mf < 4; mf++)
#pragma unroll
                for (int nf = 0; nf < 4; nf++) MMA_TF32(acc[mf][nf], af[mf], bf[nf]);
        }

        const int pf = kt + STAGES - 1;
        if (pf < nk) {
            const int ps = pf % STAGES;
            const int k0 = pf << 4;
            cp16(&As[ps * TSZ + lrow * LDA + lkb],     Ap + k0);
            cp16(&As[ps * TSZ + lrow * LDA + lkb + 4], Ap + k0 + 4);
            cp16(&Bs[ps * TSZ + lrow * LDA + lkb],     Bp + k0);
            cp16(&Bs[ps * TSZ + lrow * LDA + lkb + 4], Bp + k0 + 4);
            cp_commit();
        }
        cur = (cur + 1 == STAGES) ? 0 : cur + 1;
    }

#pragma unroll
    for (int nf = 0; nf < 4; nf++) {
        const int col = bn + wn + nf * 8 + 2 * tg;
        const float b0v = bias[col], b1v = bias[col + 1];
#pragma unroll
        for (int mf = 0; mf < 4; mf++) {
            const int row = bm + wm + mf * 16 + g;
            float v0 = acc[mf][nf][0] + b0v;
            float v1 = acc[mf][nf][1] + b1v;
            float v2 = acc[mf][nf][2] + b0v;
            float v3 = acc[mf][nf][3] + b1v;
            if (RELU) {
                v0 = fmaxf(v0, 0.f); v1 = fmaxf(v1, 0.f);
                v2 = fmaxf(v2, 0.f); v3 = fmaxf(v3, 0.f);
            }
            *(float2*)(C + (size_t)row * N + col)       = make_float2(v0, v1);
            *(float2*)(C + (size_t)(row + 8) * N + col) = make_float2(v2, v3);
        }
    }
}

// ---------------------------------------------------------------------------
// TF32 GEMM + residual + LayerNorm fused (N fixed = 256 = full row).
// out[row] = LN(resid[row] + A[row]@B^T + bias) * lns + lnb
// Block 64 rows x 256 cols, 8 warps of 32x64 (mf=2, nf=8), 3-stage cp.async.
// Row stats: quad-shfl partial -> smem[64][4] cross-warp -> rmean/rrstd.
// resid/out may alias (each element read+written by the same thread only).
// ---------------------------------------------------------------------------
#define ATSZ (64 * LDA)      // A stage words
#define BTSZ (256 * LDA)     // B stage words

__global__ __launch_bounds__(256, 2)
void tgemm_ln(const float* __restrict__ A, const float* __restrict__ Bm,
              const float* __restrict__ bias,
              const float* resid, const float* __restrict__ lns,
              const float* __restrict__ lnb, float* out,
              int M, int K) {
    extern __shared__ float smw[];
    float* As = smw;                       // [STAGES][64][LDA]
    float* Bs = smw + STAGES * ATSZ;       // [STAGES][256][LDA]

    const int bm   = blockIdx.x * 64;
    const int t    = threadIdx.x;
    const int lane = t & 31;
    const int wid  = t >> 5;
    const int wm   = (wid & 1) * 32;
    const int wn   = (wid >> 1) * 64;
    const int g    = lane >> 2;
    const int tg   = lane & 3;

    // staging: A 64 rows x 16k via 1 cp16/thread; B 256 rows x 16k via 4
    const int arow = t >> 2;            // 0..63
    const int akb  = (t & 3) * 4;       // 0,4,8,12
    const float* Ap = A  + (size_t)(bm + arow) * K + akb;
    const float* Bp = Bm + (size_t)t * K;

    float acc[2][8][4];
#pragma unroll
    for (int i = 0; i < 2; i++)
#pragma unroll
        for (int j = 0; j < 8; j++)
#pragma unroll
            for (int r = 0; r < 4; r++) acc[i][j][r] = 0.f;

    const int nk = K >> 4;
#pragma unroll
    for (int s = 0; s < STAGES - 1; s++) {
        const int k0 = s << 4;
        cp16(&As[s * ATSZ + arow * LDA + akb], Ap + k0);
#pragma unroll
        for (int j = 0; j < 4; j++)
            cp16(&Bs[s * BTSZ + t * LDA + j * 4], Bp + k0 + j * 4);
        cp_commit();
    }

    int cur = 0;
    for (int kt = 0; kt < nk; kt++) {
        if (kt < nk - 1) cp_wait<STAGES - 2>(); else cp_wait<0>();
        __syncthreads();

        const float* Ac = As + cur * ATSZ;
        const float* Bc = Bs + cur * BTSZ;
#pragma unroll
        for (int ks = 0; ks < 2; ks++) {
            const int k0 = ks * 8;
            uint32_t af[2][4], bf[8][2];
#pragma unroll
            for (int mf = 0; mf < 2; mf++) {
                const int row = wm + mf * 16 + g;
                af[mf][0] = f2tf32(Ac[row * LDA + k0 + tg]);
                af[mf][1] = f2tf32(Ac[(row + 8) * LDA + k0 + tg]);
                af[mf][2] = f2tf32(Ac[row * LDA + k0 + tg + 4]);
                af[mf][3] = f2tf32(Ac[(row + 8) * LDA + k0 + tg + 4]);
            }
#pragma unroll
            for (int nf = 0; nf < 8; nf++) {
                const int col = wn + nf * 8 + g;
                bf[nf][0] = f2tf32(Bc[col * LDA + k0 + tg]);
                bf[nf][1] = f2tf32(Bc[col * LDA + k0 + tg + 4]);
            }
#pragma unroll
            for (int mf = 0; mf < 2; mf++)
#pragma unroll
                for (int nf = 0; nf < 8; nf++) MMA_TF32(acc[mf][nf], af[mf], bf[nf]);
        }

        const int pf = kt + STAGES - 1;
        if (pf < nk) {
            const int ps = pf % STAGES;
            const int k0 = pf << 4;
            cp16(&As[ps * ATSZ + arow * LDA + akb], Ap + k0);
#pragma unroll
            for (int j = 0; j < 4; j++)
                cp16(&Bs[ps * BTSZ + t * LDA + j * 4], Bp + k0 + j * 4);
            cp_commit();
        }
        cur = (cur + 1 == STAGES) ? 0 : cur + 1;
    }

    __syncthreads();   // all fragment reads done; smem now reused for stats

    float* rsum  = smw;              // [64][4]
    float* rsq   = smw + 256;        // [64][4]
    float* rmean = smw + 512;        // [64]
    float* rrstd = smw + 576;        // [64]
    const int nidx = wid >> 1;

    // bias + residual into acc; per-row partials over this thread's 16 cols
#pragma unroll
    for (int mf = 0; mf < 2; mf++) {
        const int r0 = wm + mf * 16 + g;       // block-local rows
        const int r1 = r0 + 8;
        float s0 = 0.f, q0 = 0.f, s1 = 0.f, q1 = 0.f;
#pragma unroll
        for (int nf = 0; nf < 8; nf++) {
            const int col = wn + nf * 8 + 2 * tg;
            const float b0v = bias[col], b1v = bias[col + 1];
            const float2 e0 = *(const float2*)(resid + (size_t)(bm + r0) * E_ + col);
            const float2 e1 = *(const float2*)(resid + (size_t)(bm + r1) * E_ + col);
            float* d = acc[mf][nf];
            d[0] += b0v + e0.x;  d[1] += b1v + e0.y;
            d[2] += b0v + e1.x;  d[3] += b1v + e1.y;
            s0 += d[0] + d[1];   q0 += d[0] * d[0] + d[1] * d[1];
            s1 += d[2] + d[3];   q1 += d[2] * d[2] + d[3] * d[3];
        }
        // reduce over the tg quad (lanes differing in bits 0..1)
#pragma unroll
        for (int o = 1; o < 4; o <<= 1) {
            s0 += __shfl_xor_sync(0xffffffffu, s0, o);
            q0 += __shfl_xor_sync(0xffffffffu, q0, o);
            s1 += __shfl_xor_sync(0xffffffffu, s1, o);
            q1 += __shfl_xor_sync(0xffffffffu, q1, o);
        }
        if (tg == 0) {
            rsum[r0 * 4 + nidx] = s0;  rsq[r0 * 4 + nidx] = q0;
            rsum[r1 * 4 + nidx] = s1;  rsq[r1 * 4 + nidx] = q1;
        }
    }
    __syncthreads();

    if (t < 64) {
        const float s = rsum[t * 4] + rsum[t * 4 + 1] + rsum[t * 4 + 2] + rsum[t * 4 + 3];
        const float q = rsq[t * 4]  + rsq[t * 4 + 1]  + rsq[t * 4 + 2]  + rsq[t * 4 + 3];
        const float m = s * (1.f / E_);
        const float v = q * (1.f / E_) - m * m;
        rmean[t] = m;
        rrstd[t] = rsqrtf(v + 1e-5f);
    }
    __syncthreads();

#pragma unroll
    for (int mf = 0; mf < 2; mf++) {
        const int r0 = wm + mf * 16 + g;
        const int r1 = r0 + 8;
        const float m0 = rmean[r0], rs0 = rrstd[r0];
        const float m1 = rmean[r1], rs1 = rrstd[r1];
#pragma unroll
        for (int nf = 0; nf < 8; nf++) {
            const int col = wn + nf * 8 + 2 * tg;
            const float2 sc = *(const float2*)(lns + col);
            const float2 bi = *(const float2*)(lnb + col);
            const float* d = acc[mf][nf];
            float2 o0, o1;
            o0.x = (d[0] - m0) * rs0 * sc.x + bi.x;
            o0.y = (d[1] - m0) * rs0 * sc.y + bi.y;
            o1.x = (d[2] - m1) * rs1 * sc.x + bi.x;
            o1.y = (d[3] - m1) * rs1 * sc.y + bi.y;
            *(float2*)(out + (size_t)(bm + r0) * E_ + col) = o0;
            *(float2*)(out + (size_t)(bm + r1) * E_ + col) = o1;
        }
    }
}

// ---------------------------------------------------------------------------
// Attention: one block per (b,h), 128 threads (thread = query row).
// Single pass, no max subtraction (scores O(1); shift-invariant), masked
// keys skipped by looping k < len. K/V in smem (64KB) -> 3 CTAs/SM.
// ---------------------------------------------------------------------------
__global__ __launch_bounds__(128)
void attn_kernel(const float* __restrict__ qkv,
                 const int* __restrict__ lens,
                 float* __restrict__ out) {
    const int bh = blockIdx.x;
    const int b  = bh / H_;
    const int h  = bh % H_;
    extern __shared__ float sm[];
    float* Ks = sm;
    float* Vs = sm + S_ * HD_;

    for (int i4 = threadIdx.x; i4 < S_ * HD_ / 4; i4 += blockDim.x) {
        const int s  = i4 >> 4;
        const int d4 = i4 & 15;
        const float4* base =
            (const float4*)(qkv + (size_t)(b * S_ + s) * (3 * E_) + h * HD_);
        ((float4*)Ks)[i4] = base[(E_ / 4) + d4];
        ((float4*)Vs)[i4] = base[(2 * E_ / 4) + d4];
    }
    __syncthreads();

    const int q   = threadIdx.x;
    const int len = lens[b];

    float4 qr[16];
    {
        const float4* qp =
            (const float4*)(qkv + (size_t)(b * S_ + q) * (3 * E_) + h * HD_);
#pragma unroll
        for (int d = 0; d < 16; d++) qr[d] = qp[d];
    }

    float4 acc[16];
#pragma unroll
    for (int d = 0; d < 16; d++) acc[d] = make_float4(0.f, 0.f, 0.f, 0.f);
    float sum = 0.f;

    for (int k = 0; k < len; k++) {
        const float4* kp = (const float4*)(Ks + k * HD_);
        float s0 = 0.f, s1 = 0.f, s2 = 0.f, s3 = 0.f;
#pragma unroll
        for (int d = 0; d < 16; d += 4) {
            float4 k0 = kp[d], k1 = kp[d + 1], k2 = kp[d + 2], k3 = kp[d + 3];
            s0 += qr[d].x     * k0.x + qr[d].y     * k0.y + qr[d].z     * k0.z + qr[d].w     * k0.w;
            s1 += qr[d + 1].x * k1.x + qr[d + 1].y * k1.y + qr[d + 1].z * k1.z + qr[d + 1].w * k1.w;
            s2 += qr[d + 2].x * k2.x + qr[d + 2].y * k2.y + qr[d + 2].z * k2.z + qr[d + 2].w * k2.w;
            s3 += qr[d + 3].x * k3.x + qr[d + 3].y * k3.y + qr[d + 3].z * k3.z + qr[d + 3].w * k3.w;
        }
        const float p = __expf(((s0 + s1) + (s2 + s3)) * 0.125f);
        sum += p;
        const float4* vp = (const float4*)(Vs + k * HD_);
#pragma unroll
        for (int d = 0; d < 16; d++) {
            float4 vv = vp[d];
            acc[d].x += p * vv.x; acc[d].y += p * vv.y;
            acc[d].z += p * vv.z; acc[d].w += p * vv.w;
        }
    }
    const float inv = 1.f / sum;
    float4* op = (float4*)(out + (size_t)(b * S_ + q) * E_ + h * HD_);
#pragma unroll
    for (int d = 0; d < 16; d++) {
        float4 a = acc[d];
        a.x *= inv; a.y *= inv; a.z *= inv; a.w *= inv;
        op[d] = a;
    }
}

// ---------------------------------------------------------------------------
// Weighted pool + concat (+ per-sample sigmoid gate computed in-block)
// ---------------------------------------------------------------------------
__global__ __launch_bounds__(256)
void pool_kernel(const float* __restrict__ x, const float* __restrict__ attr_tf,
                 const int* __restrict__ lens, const int* __restrict__ lens_user,
                 const float* __restrict__ feat, const float* __restrict__ fW,
                 const float* __restrict__ fb,
                 const int* __restrict__ user_ids, const int* __restrict__ item_ids,
                 const float* __restrict__ user_emb, const float* __restrict__ item_emb,
                 float* __restrict__ out) {
    const int b = blockIdx.x;
    const int e = threadIdx.x;
    __shared__ float w[S_];
    __shared__ float wu_s;
    if (e == 0) {
        float z = fb[0];
#pragma unroll
        for (int i = 0; i < 13; i++) z += feat[b * 13 + i] * fW[i];
        wu_s = 1.f / (1.f + expf(-z));
    }
    __syncthreads();
    if (e < S_) {
        const int s = e;
        float wgt = 0.f;
        if (s < lens[b]) {
            const float g = (s < lens_user[b]) ? wu_s : (1.f - wu_s);
            wgt = attr_tf[b * S_ + s] * g;
        }
        w[s] = wgt;
    }
    __syncthreads();
    float acc = 0.f;
    const float* xb = x + (size_t)b * S_ * E_ + e;
    for (int s = 0; s < S_; s++) acc += w[s] * xb[(size_t)s * E_];
    out[(size_t)b * 3 * E_ + E_ + e]     = acc;
    out[(size_t)b * 3 * E_ + e]          = user_emb[(size_t)user_ids[b] * E_ + e];
    out[(size_t)b * 3 * E_ + 2 * E_ + e] = item_emb[(size_t)item_ids[b] * E_ + e];
}

// ---------------------------------------------------------------------------
// Scoring head: one block per sample; outv[b] staged in smem; 16 warps,
// 2 targets in flight per warp (latency hiding on the out_emb gather).
// ---------------------------------------------------------------------------
__global__ __launch_bounds__(512)
void logits_kernel(const float* __restrict__ outv, const float* __restrict__ out_emb,
                   const int* __restrict__ pos_t, const int* __restrict__ pos_l,
                   const int* __restrict__ neg_t, const int* __restrict__ neg_l,
                   float* __restrict__ dout) {
    const int b    = blockIdx.x;
    const int t    = threadIdx.x;
    const int warp = t >> 5;
    const int lane = t & 31;
    __shared__ float ov[3 * E_];
    for (int i = t; i < 3 * E_; i += 512) ov[i] = outv[(size_t)b * 3 * E_ + i];
    __syncthreads();

    const int pl = pos_l[b];
    const int nl = neg_l[b];
    const float4* ovs = (const float4*)ov;

    for (int j = warp; j < NT_; j += 32) {
        const int j2 = j + 16;
        int tgt1; float valid1, pos1;
        if (j < P_) {
            tgt1 = pos_t[b * P_ + j]; valid1 = (j < pl) ? 1.f : 0.f; pos1 = 1.f;
        } else {
            const int jn = j - P_;
            tgt1 = neg_t[b * N_ + jn]; valid1 = (jn < nl) ? 1.f : 0.f; pos1 = 0.f;
        }
        const bool have2 = (j2 < NT_);
        int tgt2 = 0; float valid2 = 0.f, pos2 = 0.f;
        if (have2) {
            if (j2 < P_) {
                tgt2 = pos_t[b * P_ + j2]; valid2 = (j2 < pl) ? 1.f : 0.f; pos2 = 1.f;
            } else {
                const int jn = j2 - P_;
                tgt2 = neg_t[b * N_ + jn]; valid2 = (jn < nl) ? 1.f : 0.f; pos2 = 0.f;
            }
        }
        const float4* e1 = (const float4*)(out_emb + (size_t)tgt1 * (3 * E_));
        const float4* e2 = (const float4*)(out_emb + (size_t)tgt2 * (3 * E_));
        float a1 = 0.f, a2 = 0.f;
#pragma unroll
        for (int i = 0; i < 6; i++) {
            const int k4 = lane + i * 32;
            const float4 c = ovs[k4];
            float4 r1 = e1[k4];
            a1 += r1.x * c.x + r1.y * c.y + r1.z * c.z + r1.w * c.w;
            if (have2) {
                float4 r2 = e2[k4];
                a2 += r2.x * c.x + r2.y * c.y + r2.z * c.z + r2.w * c.w;
            }
        }
#pragma unroll
        for (int o = 16; o; o >>= 1) {
            a1 += __shfl_xor_sync(0xffffffffu, a1, o);
            a2 += __shfl_xor_sync(0xffffffffu, a2, o);
        }
        if (lane == 0) {
            const int idx = b * NT_ + j;
            dout[idx]                = a1;
            dout[B_ * NT_ + idx]     = valid1;
            dout[2 * B_ * NT_ + idx] = pos1 * valid1;
            if (have2) {
                const int idx2 = b * NT_ + j2;
                dout[idx2]                = a2;
                dout[B_ * NT_ + idx2]     = valid2;
                dout[2 * B_ * NT_ + idx2] = pos2 * valid2;
            }
        }
    }
}

// ---------------------------------------------------------------------------
// Launch
// ---------------------------------------------------------------------------
extern "C" void kernel_launch(void* const* d_in, const int* in_sizes, int n_in,
                              void* d_out, int out_size) {
    const int*   attr           = (const int*)  d_in[0];
    const float* attr_tf        = (const float*)d_in[2];
    const float* attr_feat      = (const float*)d_in[3];
    const int*   attr_lens      = (const int*)  d_in[4];
    const int*   attr_lens_user = (const int*)  d_in[5];
    const int*   user_ids       = (const int*)  d_in[7];
    const int*   item_ids       = (const int*)  d_in[8];
    const int*   pos_targets    = (const int*)  d_in[9];
    const int*   pos_lens       = (const int*)  d_in[10];
    const int*   neg_targets    = (const int*)  d_in[11];
    const int*   neg_lens       = (const int*)  d_in[12];
    const float* attr_emb       = (const float*)d_in[13];
    const float* user_emb       = (const float*)d_in[14];
    const float* item_emb       = (const float*)d_in[15];
    const float* out_emb        = (const float*)d_in[16];
    const float* fw_W           = (const float*)d_in[17];
    const float* fw_b           = (const float*)d_in[18];
    const float* qkv_w          = (const float*)d_in[19];
    const float* qkv_b          = (const float*)d_in[20];
    const float* attn_out_w     = (const float*)d_in[21];
    const float* attn_out_b     = (const float*)d_in[22];
    const float* ln1_s          = (const float*)d_in[23];
    const float* ln1_b          = (const float*)d_in[24];
    const float* ff1_w          = (const float*)d_in[25];
    const float* ff1_b          = (const float*)d_in[26];
    const float* ff2_w          = (const float*)d_in[27];
    const float* ff2_b          = (const float*)d_in[28];
    const float* ln2_s          = (const float*)d_in[29];
    const float* ln2_b          = (const float*)d_in[30];

    float *x, *qkv, *attn, *ff, *outv;
    cudaGetSymbolAddress((void**)&x,    g_x);
    cudaGetSymbolAddress((void**)&qkv,  g_qkv);
    cudaGetSymbolAddress((void**)&attn, g_attn);
    cudaGetSymbolAddress((void**)&ff,   g_ff);
    cudaGetSymbolAddress((void**)&outv, g_out);

    const int gemm_smem = STAGES * 2 * TSZ * (int)sizeof(float);          // 61440
    cudaFuncSetAttribute(tgemm<false>, cudaFuncAttributeMaxDynamicSharedMemorySize,
                         gemm_smem);
    cudaFuncSetAttribute(tgemm<true>, cudaFuncAttributeMaxDynamicSharedMemorySize,
                         gemm_smem);
    const int ln_smem = STAGES * (ATSZ + BTSZ) * (int)sizeof(float);      // 76800
    cudaFuncSetAttribute(tgemm_ln, cudaFuncAttributeMaxDynamicSharedMemorySize,
                         ln_smem);
    const int attn_smem = 2 * S_ * HD_ * (int)sizeof(float);              // 64KB
    cudaFuncSetAttribute(attn_kernel, cudaFuncAttributeMaxDynamicSharedMemorySize,
                         attn_smem);

    gather_kernel<<<(T_ * E_ / 4 + 255) / 256, 256>>>(attr, attr_emb, x);

    for (int l = 0; l < L_; l++) {
        const float* lqkv_w = qkv_w      + (size_t)l * 3 * E_ * E_;
        const float* lqkv_b = qkv_b      + (size_t)l * 3 * E_;
        const float* lao_w  = attn_out_w + (size_t)l * E_ * E_;
        const float* lao_b  = attn_out_b + (size_t)l * E_;
        const float* l1s    = ln1_s + (size_t)l * E_;
        const float* l1b    = ln1_b + (size_t)l * E_;
        const float* lf1_w  = ff1_w + (size_t)l * F_ * E_;
        const float* lf1_b  = ff1_b + (size_t)l * F_;
        const float* lf2_w  = ff2_w + (size_t)l * E_ * F_;
        const float* lf2_b  = ff2_b + (size_t)l * E_;
        const float* l2s    = ln2_s + (size_t)l * E_;
        const float* l2b    = ln2_b + (size_t)l * E_;

        tgemm<false><<<dim3(3 * E_ / 128, T_ / 128), 256, gemm_smem>>>(
            x, lqkv_w, lqkv_b, qkv, T_, 3 * E_, E_);
        attn_kernel<<<B_ * H_, S_, attn_smem>>>(qkv, attr_lens, attn);
        // x = LN(x + attn @ Wo^T + bo)
        tgemm_ln<<<T_ / 64, 256, ln_smem>>>(
            attn, lao_w, lao_b, x, l1s, l1b, x, T_, E_);
        tgemm<true><<<dim3(F_ / 128, T_ / 128), 256, gemm_smem>>>(
            x, lf1_w, lf1_b, ff, T_, F_, E_);
        // x = LN(x + ff @ W2^T + b2)
        tgemm_ln<<<T_ / 64, 256, ln_smem>>>(
            ff, lf2_w, lf2_b, x, l2s, l2b, x, T_, F_);
    }

    pool_kernel<<<B_, 256>>>(x, attr_tf, attr_lens, attr_lens_user,
                             attr_feat, fw_W, fw_b,
                             user_ids, item_ids, user_emb, item_emb, outv);

    logits_kernel<<<B_, 512>>>(
        outv, out_emb, pos_targets, pos_lens, neg_targets, neg_lens,
        (float*)d_out);
}

// round 8
// speedup vs baseline: 1.2177x; 1.2177x over previous
#include <cuda_runtime.h>
#include <cuda_bf16.h>
#include <math.h>
#include <stdint.h>

// Problem constants
#define B_   256
#define S_   128
#define P_   100
#define N_   500
#define E_   256
#define H_   4
#define HD_  64
#define L_   2
#define F_   1024
#define T_   (B_ * S_)      // 32768 tokens
#define NT_  (P_ + N_)      // 600 targets

// ---------------------------------------------------------------------------
// Scratch (device globals — no allocation allowed)
// ---------------------------------------------------------------------------
__device__ float g_x   [(size_t)T_ * E_];
__device__ float g_qkv [(size_t)T_ * 3 * E_];
__device__ float g_attn[(size_t)T_ * E_];
__device__ float g_tmp [(size_t)T_ * E_];
__device__ float g_ff  [(size_t)T_ * F_];
__device__ float g_out [(size_t)B_ * 3 * E_];

// ---------------------------------------------------------------------------
// cp.async + tf32 helpers
// ---------------------------------------------------------------------------
__device__ __forceinline__ void cp16(void* sdst, const void* gsrc) {
    uint32_t s = (uint32_t)__cvta_generic_to_shared(sdst);
    asm volatile("cp.async.cg.shared.global [%0], [%1], 16;\n" :: "r"(s), "l"(gsrc));
}
__device__ __forceinline__ void cp_commit() {
    asm volatile("cp.async.commit_group;\n");
}
template<int NWait>
__device__ __forceinline__ void cp_wait() {
    asm volatile("cp.async.wait_group %0;\n" :: "n"(NWait));
}
__device__ __forceinline__ uint32_t f2tf32(float x) {
    uint32_t r;
    asm("cvt.rna.tf32.f32 %0, %1;" : "=r"(r) : "f"(x));
    return r;
}
#define MMA_TF32(d, a, b)                                                     \
    asm volatile(                                                             \
        "mma.sync.aligned.m16n8k8.row.col.f32.tf32.tf32.f32 "                 \
        "{%0,%1,%2,%3}, {%4,%5,%6,%7}, {%8,%9}, {%0,%1,%2,%3};"               \
        : "+f"(d[0]), "+f"(d[1]), "+f"(d[2]), "+f"(d[3])                      \
        : "r"(a[0]), "r"(a[1]), "r"(a[2]), "r"(a[3]), "r"(b[0]), "r"(b[1]))

// ---------------------------------------------------------------------------
// Embedding gather (float4)
// ---------------------------------------------------------------------------
__global__ void gather_kernel(const int* __restrict__ attr,
                              const float* __restrict__ emb,
                              float* __restrict__ x) {
    int i4 = blockIdx.x * blockDim.x + threadIdx.x;
    if (i4 < T_ * (E_ / 4)) {
        int t = i4 >> 6;
        int e4 = i4 & 63;
        ((float4*)x)[i4] = ((const float4*)emb)[(size_t)attr[t] * (E_ / 4) + e4];
    }
}

// ---------------------------------------------------------------------------
// TF32 GEMM: C = A @ B^T + bias (opt ReLU). Block 128x128, BK=16, 8 warps
// of 64x32, 3-stage cp.async, 2 CTAs/SM.  (R6-proven)
// ---------------------------------------------------------------------------
#define LDA    20
#define TSZ    (128 * LDA)
#define STAGES 3

template<bool RELU>
__global__ __launch_bounds__(256, 2)
void tgemm(const float* __restrict__ A, const float* __restrict__ Bm,
           const float* __restrict__ bias, float* __restrict__ C,
           int M, int N, int K) {
    extern __shared__ float smw[];
    float* As = smw;
    float* Bs = smw + STAGES * TSZ;

    const int bm   = blockIdx.y * 128;
    const int bn   = blockIdx.x * 128;
    const int t    = threadIdx.x;
    const int lane = t & 31;
    const int wid  = t >> 5;
    const int wm   = (wid & 1) * 64;
    const int wn   = (wid >> 1) * 32;
    const int g    = lane >> 2;
    const int tg   = lane & 3;

    const int lrow = t >> 1;
    const int lkb  = (t & 1) * 8;
    const float* Ap = A  + (size_t)(bm + lrow) * K + lkb;
    const float* Bp = Bm + (size_t)(bn + lrow) * K + lkb;

    float acc[4][4][4];
#pragma unroll
    for (int i = 0; i < 4; i++)
#pragma unroll
        for (int j = 0; j < 4; j++)
#pragma unroll
            for (int r = 0; r < 4; r++) acc[i][j][r] = 0.f;

    const int nk = K >> 4;
#pragma unroll
    for (int s = 0; s < STAGES - 1; s++) {
        const int k0 = s << 4;
        cp16(&As[s * TSZ + lrow * LDA + lkb],     Ap + k0);
        cp16(&As[s * TSZ + lrow * LDA + lkb + 4], Ap + k0 + 4);
        cp16(&Bs[s * TSZ + lrow * LDA + lkb],     Bp + k0);
        cp16(&Bs[s * TSZ + lrow * LDA + lkb + 4], Bp + k0 + 4);
        cp_commit();
    }

    int cur = 0;
    for (int kt = 0; kt < nk; kt++) {
        if (kt < nk - 1) cp_wait<STAGES - 2>(); else cp_wait<0>();
        __syncthreads();

        const float* Ac = As + cur * TSZ;
        const float* Bc = Bs + cur * TSZ;
#pragma unroll
        for (int ks = 0; ks < 2; ks++) {
            const int k0 = ks * 8;
            uint32_t af[4][4], bf[4][2];
#pragma unroll
            for (int mf = 0; mf < 4; mf++) {
                const int row = wm + mf * 16 + g;
                af[mf][0] = f2tf32(Ac[row * LDA + k0 + tg]);
                af[mf][1] = f2tf32(Ac[(row + 8) * LDA + k0 + tg]);
                af[mf][2] = f2tf32(Ac[row * LDA + k0 + tg + 4]);
                af[mf][3] = f2tf32(Ac[(row + 8) * LDA + k0 + tg + 4]);
            }
#pragma unroll
            for (int nf = 0; nf < 4; nf++) {
                const int col = wn + nf * 8 + g;
                bf[nf][0] = f2tf32(Bc[col * LDA + k0 + tg]);
                bf[nf][1] = f2tf32(Bc[col * LDA + k0 + tg + 4]);
            }
#pragma unroll
            for (int mf = 0; mf < 4; mf++)
#pragma unroll
                for (int nf = 0; nf < 4; nf++) MMA_TF32(acc[mf][nf], af[mf], bf[nf]);
        }

        const int pf = kt + STAGES - 1;
        if (pf < nk) {
            const int ps = pf % STAGES;
            const int k0 = pf << 4;
            cp16(&As[ps * TSZ + lrow * LDA + lkb],     Ap + k0);
            cp16(&As[ps * TSZ + lrow * LDA + lkb + 4], Ap + k0 + 4);
            cp16(&Bs[ps * TSZ + lrow * LDA + lkb],     Bp + k0);
            cp16(&Bs[ps * TSZ + lrow * LDA + lkb + 4], Bp + k0 + 4);
            cp_commit();
        }
        cur = (cur + 1 == STAGES) ? 0 : cur + 1;
    }

#pragma unroll
    for (int nf = 0; nf < 4; nf++) {
        const int col = bn + wn + nf * 8 + 2 * tg;
        const float b0v = bias[col], b1v = bias[col + 1];
#pragma unroll
        for (int mf = 0; mf < 4; mf++) {
            const int row = bm + wm + mf * 16 + g;
            float v0 = acc[mf][nf][0] + b0v;
            float v1 = acc[mf][nf][1] + b1v;
            float v2 = acc[mf][nf][2] + b0v;
            float v3 = acc[mf][nf][3] + b1v;
            if (RELU) {
                v0 = fmaxf(v0, 0.f); v1 = fmaxf(v1, 0.f);
                v2 = fmaxf(v2, 0.f); v3 = fmaxf(v3, 0.f);
            }
            *(float2*)(C + (size_t)row * N + col)       = make_float2(v0, v1);
            *(float2*)(C + (size_t)(row + 8) * N + col) = make_float2(v2, v3);
        }
    }
}

// ---------------------------------------------------------------------------
// Tensor-core attention: one block per (b,h), 256 threads (8 warps).
// Phase 1: S = Q@K^T (128x128x64) tf32 MMA, warp tile 64x32.
// exp(0.125*s) in regs (no max-sub; scores O(1)), masked keys -> 0.
// Row sums via quad-shfl + smem partials. P -> smem (overlays Q/K).
// Phase 2: O = P@V (128x64x128), warp tile 32x32, V transposed in smem.
// Normalization (1/rowsum) applied at the store.
// ---------------------------------------------------------------------------
#define QLD 68            // Q/K row stride (floats)
#define PLD2 132          // P/Vt row stride (floats)
#define VT_OFF 0                              // Vt: 64 x PLD2
#define Q_OFF  (64 * PLD2)                    // 8448: Q 128 x QLD
#define K_OFF  (Q_OFF + 128 * QLD)            // 17152
#define P_OFF  Q_OFF                          // overlays Q+K (16896 <= 17408)
#define PART_OFF (K_OFF + 128 * QLD)          // 25856: [128][4]
#define RSUM_OFF (PART_OFF + 512)             // 26368: [128]
#define ATTN_SMEMF (RSUM_OFF + 128)           // 26496 floats = 105984 B

__global__ __launch_bounds__(256)
void attn_kernel(const float* __restrict__ qkv,
                 const int* __restrict__ lens,
                 float* __restrict__ out) {
    const int bh = blockIdx.x;
    const int b  = bh / H_;
    const int h  = bh % H_;
    extern __shared__ float sm[];

    const int t    = threadIdx.x;
    const int lane = t & 31;
    const int wid  = t >> 5;
    const int g    = lane >> 2;
    const int tg   = lane & 3;
    const int len  = lens[b];

    // ---- load Q, K (row-major, stride QLD) and V transposed (Vt[d][k]) ----
    for (int i4 = t; i4 < S_ * HD_ / 4; i4 += 256) {   // 2048 float4 per matrix
        const int s  = i4 >> 4;
        const int d4 = i4 & 15;
        const float4* base =
            (const float4*)(qkv + (size_t)(b * S_ + s) * (3 * E_) + h * HD_);
        float4 qv = base[d4];
        float4 kv = base[(E_ / 4) + d4];
        float4 vv = base[(2 * E_ / 4) + d4];
        *(float4*)&sm[Q_OFF + s * QLD + d4 * 4] = qv;
        *(float4*)&sm[K_OFF + s * QLD + d4 * 4] = kv;
        const int d0 = d4 * 4;
        sm[VT_OFF + (d0 + 0) * PLD2 + s] = vv.x;
        sm[VT_OFF + (d0 + 1) * PLD2 + s] = vv.y;
        sm[VT_OFF + (d0 + 2) * PLD2 + s] = vv.z;
        sm[VT_OFF + (d0 + 3) * PLD2 + s] = vv.w;
    }
    __syncthreads();

    // ---- phase 1: S = Q @ K^T, warp tile 64(q) x 32(k) ----
    const int wm = (wid & 1) * 64;
    const int wn = (wid >> 1) * 32;
    float acc[4][4][4];
#pragma unroll
    for (int i = 0; i < 4; i++)
#pragma unroll
        for (int j = 0; j < 4; j++)
#pragma unroll
            for (int r = 0; r < 4; r++) acc[i][j][r] = 0.f;

#pragma unroll
    for (int ks = 0; ks < 8; ks++) {
        const int k0 = ks * 8;
        uint32_t af[4][4], bf[4][2];
#pragma unroll
        for (int mf = 0; mf < 4; mf++) {
            const int row = wm + mf * 16 + g;
            af[mf][0] = f2tf32(sm[Q_OFF + row * QLD + k0 + tg]);
            af[mf][1] = f2tf32(sm[Q_OFF + (row + 8) * QLD + k0 + tg]);
            af[mf][2] = f2tf32(sm[Q_OFF + row * QLD + k0 + tg + 4]);
            af[mf][3] = f2tf32(sm[Q_OFF + (row + 8) * QLD + k0 + tg + 4]);
        }
#pragma unroll
        for (int nf = 0; nf < 4; nf++) {
            const int col = wn + nf * 8 + g;
            bf[nf][0] = f2tf32(sm[K_OFF + col * QLD + k0 + tg]);
            bf[nf][1] = f2tf32(sm[K_OFF + col * QLD + k0 + tg + 4]);
        }
#pragma unroll
        for (int mf = 0; mf < 4; mf++)
#pragma unroll
            for (int nf = 0; nf < 4; nf++) MMA_TF32(acc[mf][nf], af[mf], bf[nf]);
    }

    // ---- exp + row partial sums (in regs) ----
    float rs[4][2];   // per mf: rows r0 (g) and r1 (g+8)
#pragma unroll
    for (int mf = 0; mf < 4; mf++) { rs[mf][0] = 0.f; rs[mf][1] = 0.f; }
#pragma unroll
    for (int mf = 0; mf < 4; mf++) {
#pragma unroll
        for (int nf = 0; nf < 4; nf++) {
            const int c0 = wn + nf * 8 + 2 * tg;
            const int c1 = c0 + 1;
            float* d = acc[mf][nf];
            d[0] = (c0 < len) ? __expf(d[0] * 0.125f) : 0.f;
            d[1] = (c1 < len) ? __expf(d[1] * 0.125f) : 0.f;
            d[2] = (c0 < len) ? __expf(d[2] * 0.125f) : 0.f;
            d[3] = (c1 < len) ? __expf(d[3] * 0.125f) : 0.f;
            rs[mf][0] += d[0] + d[1];
            rs[mf][1] += d[2] + d[3];
        }
        // quad reduce over tg
#pragma unroll
        for (int o = 1; o < 4; o <<= 1) {
            rs[mf][0] += __shfl_xor_sync(0xffffffffu, rs[mf][0], o);
            rs[mf][1] += __shfl_xor_sync(0xffffffffu, rs[mf][1], o);
        }
    }
    __syncthreads();   // everyone done reading Q/K -> safe to overlay with P

    // ---- write P and row partials ----
    const int nidx = wid >> 1;   // which 32-key slab
#pragma unroll
    for (int mf = 0; mf < 4; mf++) {
        const int r0 = wm + mf * 16 + g;
        const int r1 = r0 + 8;
#pragma unroll
        for (int nf = 0; nf < 4; nf++) {
            const int c0 = wn + nf * 8 + 2 * tg;
            const float* d = acc[mf][nf];
            *(float2*)&sm[P_OFF + r0 * PLD2 + c0] = make_float2(d[0], d[1]);
            *(float2*)&sm[P_OFF + r1 * PLD2 + c0] = make_float2(d[2], d[3]);
        }
        if (tg == 0) {
            sm[PART_OFF + r0 * 4 + nidx] = rs[mf][0];
            sm[PART_OFF + r1 * 4 + nidx] = rs[mf][1];
        }
    }
    __syncthreads();

    if (t < 128) {
        const float s = sm[PART_OFF + t * 4] + sm[PART_OFF + t * 4 + 1] +
                        sm[PART_OFF + t * 4 + 2] + sm[PART_OFF + t * 4 + 3];
        sm[RSUM_OFF + t] = 1.f / s;
    }
    __syncthreads();

    // ---- phase 2: O = P @ V, warp tile 32(q) x 32(d) ----
    const int wm2 = (wid & 3) * 32;
    const int wn2 = (wid >> 2) * 32;
    float acc2[2][4][4];
#pragma unroll
    for (int i = 0; i < 2; i++)
#pragma unroll
        for (int j = 0; j < 4; j++)
#pragma unroll
            for (int r = 0; r < 4; r++) acc2[i][j][r] = 0.f;

#pragma unroll
    for (int ks = 0; ks < 16; ks++) {
        const int k0 = ks * 8;
        uint32_t af[2][4], bf[4][2];
#pragma unroll
        for (int mf = 0; mf < 2; mf++) {
            const int row = wm2 + mf * 16 + g;
            af[mf][0] = f2tf32(sm[P_OFF + row * PLD2 + k0 + tg]);
            af[mf][1] = f2tf32(sm[P_OFF + (row + 8) * PLD2 + k0 + tg]);
            af[mf][2] = f2tf32(sm[P_OFF + row * PLD2 + k0 + tg + 4]);
            af[mf][3] = f2tf32(sm[P_OFF + (row + 8) * PLD2 + k0 + tg + 4]);
        }
#pragma unroll
        for (int nf = 0; nf < 4; nf++) {
            const int col = wn2 + nf * 8 + g;
            bf[nf][0] = f2tf32(sm[VT_OFF + col * PLD2 + k0 + tg]);
            bf[nf][1] = f2tf32(sm[VT_OFF + col * PLD2 + k0 + tg + 4]);
        }
#pragma unroll
        for (int mf = 0; mf < 2; mf++)
#pragma unroll
            for (int nf = 0; nf < 4; nf++) MMA_TF32(acc2[mf][nf], af[mf], bf[nf]);
    }

    // ---- normalize + store ----
#pragma unroll
    for (int mf = 0; mf < 2; mf++) {
        const int r0 = wm2 + mf * 16 + g;
        const int r1 = r0 + 8;
        const float i0 = sm[RSUM_OFF + r0];
        const float i1 = sm[RSUM_OFF + r1];
#pragma unroll
        for (int nf = 0; nf < 4; nf++) {
            const int c = wn2 + nf * 8 + 2 * tg;
            const float* d = acc2[mf][nf];
            *(float2*)(out + (size_t)(b * S_ + r0) * E_ + h * HD_ + c) =
                make_float2(d[0] * i0, d[1] * i0);
            *(float2*)(out + (size_t)(b * S_ + r1) * E_ + h * HD_ + c) =
                make_float2(d[2] * i1, d[3] * i1);
        }
    }
}

// ---------------------------------------------------------------------------
// Fused residual add + LayerNorm: warp per token, 8 tokens per block
// ---------------------------------------------------------------------------
__global__ __launch_bounds__(256)
void add_ln_kernel(const float* __restrict__ x, const float* __restrict__ y,
                   const float* __restrict__ sc, const float* __restrict__ bi,
                   float* __restrict__ out) {
    const int tok  = blockIdx.x * 8 + (threadIdx.x >> 5);
    const int lane = threadIdx.x & 31;
    const size_t base4 = (size_t)tok * (E_ / 4);

    float4 v0 = ((const float4*)x)[base4 + lane];
    float4 v1 = ((const float4*)x)[base4 + 32 + lane];
    float4 y0 = ((const float4*)y)[base4 + lane];
    float4 y1 = ((const float4*)y)[base4 + 32 + lane];
    v0.x += y0.x; v0.y += y0.y; v0.z += y0.z; v0.w += y0.w;
    v1.x += y1.x; v1.y += y1.y; v1.z += y1.z; v1.w += y1.w;

    float s = v0.x + v0.y + v0.z + v0.w + v1.x + v1.y + v1.z + v1.w;
#pragma unroll
    for (int o = 16; o; o >>= 1) s += __shfl_xor_sync(0xffffffffu, s, o);
    const float m = s * (1.f / E_);

    float q =
        (v0.x - m) * (v0.x - m) + (v0.y - m) * (v0.y - m) +
        (v0.z - m) * (v0.z - m) + (v0.w - m) * (v0.w - m) +
        (v1.x - m) * (v1.x - m) + (v1.y - m) * (v1.y - m) +
        (v1.z - m) * (v1.z - m) + (v1.w - m) * (v1.w - m);
#pragma unroll
    for (int o = 16; o; o >>= 1) q += __shfl_xor_sync(0xffffffffu, q, o);
    const float rstd = rsqrtf(q * (1.f / E_) + 1e-5f);

    const float4 s0 = ((const float4*)sc)[lane];
    const float4 s1 = ((const float4*)sc)[32 + lane];
    const float4 b0 = ((const float4*)bi)[lane];
    const float4 b1 = ((const float4*)bi)[32 + lane];
    float4 o0, o1;
    o0.x = (v0.x - m) * rstd * s0.x + b0.x;
    o0.y = (v0.y - m) * rstd * s0.y + b0.y;
    o0.z = (v0.z - m) * rstd * s0.z + b0.z;
    o0.w = (v0.w - m) * rstd * s0.w + b0.w;
    o1.x = (v1.x - m) * rstd * s1.x + b1.x;
    o1.y = (v1.y - m) * rstd * s1.y + b1.y;
    o1.z = (v1.z - m) * rstd * s1.z + b1.z;
    o1.w = (v1.w - m) * rstd * s1.w + b1.w;
    ((float4*)out)[base4 + lane]      = o0;
    ((float4*)out)[base4 + 32 + lane] = o1;
}

// ---------------------------------------------------------------------------
// Weighted pool + concat (+ per-sample sigmoid gate computed in-block)
// ---------------------------------------------------------------------------
__global__ __launch_bounds__(256)
void pool_kernel(const float* __restrict__ x, const float* __restrict__ attr_tf,
                 const int* __restrict__ lens, const int* __restrict__ lens_user,
                 const float* __restrict__ feat, const float* __restrict__ fW,
                 const float* __restrict__ fb,
                 const int* __restrict__ user_ids, const int* __restrict__ item_ids,
                 const float* __restrict__ user_emb, const float* __restrict__ item_emb,
                 float* __restrict__ out) {
    const int b = blockIdx.x;
    const int e = threadIdx.x;
    __shared__ float w[S_];
    __shared__ float wu_s;
    if (e == 0) {
        float z = fb[0];
#pragma unroll
        for (int i = 0; i < 13; i++) z += feat[b * 13 + i] * fW[i];
        wu_s = 1.f / (1.f + expf(-z));
    }
    __syncthreads();
    if (e < S_) {
        const int s = e;
        float wgt = 0.f;
        if (s < lens[b]) {
            const float g = (s < lens_user[b]) ? wu_s : (1.f - wu_s);
            wgt = attr_tf[b * S_ + s] * g;
        }
        w[s] = wgt;
    }
    __syncthreads();
    float acc = 0.f;
    const float* xb = x + (size_t)b * S_ * E_ + e;
    for (int s = 0; s < S_; s++) acc += w[s] * xb[(size_t)s * E_];
    out[(size_t)b * 3 * E_ + E_ + e]     = acc;
    out[(size_t)b * 3 * E_ + e]          = user_emb[(size_t)user_ids[b] * E_ + e];
    out[(size_t)b * 3 * E_ + 2 * E_ + e] = item_emb[(size_t)item_ids[b] * E_ + e];
}

// ---------------------------------------------------------------------------
// Scoring head: one block per sample; outv[b] staged in smem; 16 warps,
// 2 targets in flight per warp.
// ---------------------------------------------------------------------------
__global__ __launch_bounds__(512)
void logits_kernel(const float* __restrict__ outv, const float* __restrict__ out_emb,
                   const int* __restrict__ pos_t, const int* __restrict__ pos_l,
                   const int* __restrict__ neg_t, const int* __restrict__ neg_l,
                   float* __restrict__ dout) {
    const int b    = blockIdx.x;
    const int t    = threadIdx.x;
    const int warp = t >> 5;
    const int lane = t & 31;
    __shared__ float ov[3 * E_];
    for (int i = t; i < 3 * E_; i += 512) ov[i] = outv[(size_t)b * 3 * E_ + i];
    __syncthreads();

    const int pl = pos_l[b];
    const int nl = neg_l[b];
    const float4* ovs = (const float4*)ov;

    for (int j = warp; j < NT_; j += 32) {
        const int j2 = j + 16;
        int tgt1; float valid1, pos1;
        if (j < P_) {
            tgt1 = pos_t[b * P_ + j]; valid1 = (j < pl) ? 1.f : 0.f; pos1 = 1.f;
        } else {
            const int jn = j - P_;
            tgt1 = neg_t[b * N_ + jn]; valid1 = (jn < nl) ? 1.f : 0.f; pos1 = 0.f;
        }
        const bool have2 = (j2 < NT_);
        int tgt2 = 0; float valid2 = 0.f, pos2 = 0.f;
        if (have2) {
            if (j2 < P_) {
                tgt2 = pos_t[b * P_ + j2]; valid2 = (j2 < pl) ? 1.f : 0.f; pos2 = 1.f;
            } else {
                const int jn = j2 - P_;
                tgt2 = neg_t[b * N_ + jn]; valid2 = (jn < nl) ? 1.f : 0.f; pos2 = 0.f;
            }
        }
        const float4* e1 = (const float4*)(out_emb + (size_t)tgt1 * (3 * E_));
        const float4* e2 = (const float4*)(out_emb + (size_t)tgt2 * (3 * E_));
        float a1 = 0.f, a2 = 0.f;
#pragma unroll
        for (int i = 0; i < 6; i++) {
            const int k4 = lane + i * 32;
            const float4 c = ovs[k4];
            float4 r1 = e1[k4];
            a1 += r1.x * c.x + r1.y * c.y + r1.z * c.z + r1.w * c.w;
            if (have2) {
                float4 r2 = e2[k4];
                a2 += r2.x * c.x + r2.y * c.y + r2.z * c.z + r2.w * c.w;
            }
        }
#pragma unroll
        for (int o = 16; o; o >>= 1) {
            a1 += __shfl_xor_sync(0xffffffffu, a1, o);
            a2 += __shfl_xor_sync(0xffffffffu, a2, o);
        }
        if (lane == 0) {
            const int idx = b * NT_ + j;
            dout[idx]                = a1;
            dout[B_ * NT_ + idx]     = valid1;
            dout[2 * B_ * NT_ + idx] = pos1 * valid1;
            if (have2) {
                const int idx2 = b * NT_ + j2;
                dout[idx2]                = a2;
                dout[B_ * NT_ + idx2]     = valid2;
                dout[2 * B_ * NT_ + idx2] = pos2 * valid2;
            }
        }
    }
}

// ---------------------------------------------------------------------------
// Launch
// ---------------------------------------------------------------------------
extern "C" void kernel_launch(void* const* d_in, const int* in_sizes, int n_in,
                              void* d_out, int out_size) {
    const int*   attr           = (const int*)  d_in[0];
    const float* attr_tf        = (const float*)d_in[2];
    const float* attr_feat      = (const float*)d_in[3];
    const int*   attr_lens      = (const int*)  d_in[4];
    const int*   attr_lens_user = (const int*)  d_in[5];
    const int*   user_ids       = (const int*)  d_in[7];
    const int*   item_ids       = (const int*)  d_in[8];
    const int*   pos_targets    = (const int*)  d_in[9];
    const int*   pos_lens       = (const int*)  d_in[10];
    const int*   neg_targets    = (const int*)  d_in[11];
    const int*   neg_lens       = (const int*)  d_in[12];
    const float* attr_emb       = (const float*)d_in[13];
    const float* user_emb       = (const float*)d_in[14];
    const float* item_emb       = (const float*)d_in[15];
    const float* out_emb        = (const float*)d_in[16];
    const float* fw_W           = (const float*)d_in[17];
    const float* fw_b           = (const float*)d_in[18];
    const float* qkv_w          = (const float*)d_in[19];
    const float* qkv_b          = (const float*)d_in[20];
    const float* attn_out_w     = (const float*)d_in[21];
    const float* attn_out_b     = (const float*)d_in[22];
    const float* ln1_s          = (const float*)d_in[23];
    const float* ln1_b          = (const float*)d_in[24];
    const float* ff1_w          = (const float*)d_in[25];
    const float* ff1_b          = (const float*)d_in[26];
    const float* ff2_w          = (const float*)d_in[27];
    const float* ff2_b          = (const float*)d_in[28];
    const float* ln2_s          = (const float*)d_in[29];
    const float* ln2_b          = (const float*)d_in[30];

    float *x, *qkv, *attn, *tmp, *ff, *outv;
    cudaGetSymbolAddress((void**)&x,    g_x);
    cudaGetSymbolAddress((void**)&qkv,  g_qkv);
    cudaGetSymbolAddress((void**)&attn, g_attn);
    cudaGetSymbolAddress((void**)&tmp,  g_tmp);
    cudaGetSymbolAddress((void**)&ff,   g_ff);
    cudaGetSymbolAddress((void**)&outv, g_out);

    const int gemm_smem = STAGES * 2 * TSZ * (int)sizeof(float);   // 61440
    cudaFuncSetAttribute(tgemm<false>, cudaFuncAttributeMaxDynamicSharedMemorySize,
                         gemm_smem);
    cudaFuncSetAttribute(tgemm<true>, cudaFuncAttributeMaxDynamicSharedMemorySize,
                         gemm_smem);
    const int attn_smem = ATTN_SMEMF * (int)sizeof(float);         // 105984
    cudaFuncSetAttribute(attn_kernel, cudaFuncAttributeMaxDynamicSharedMemorySize,
                         attn_smem);

    gather_kernel<<<(T_ * E_ / 4 + 255) / 256, 256>>>(attr, attr_emb, x);

    for (int l = 0; l < L_; l++) {
        const float* lqkv_w = qkv_w      + (size_t)l * 3 * E_ * E_;
        const float* lqkv_b = qkv_b      + (size_t)l * 3 * E_;
        const float* lao_w  = attn_out_w + (size_t)l * E_ * E_;
        const float* lao_b  = attn_out_b + (size_t)l * E_;
        const float* l1s    = ln1_s + (size_t)l * E_;
        const float* l1b    = ln1_b + (size_t)l * E_;
        const float* lf1_w  = ff1_w + (size_t)l * F_ * E_;
        const float* lf1_b  = ff1_b + (size_t)l * F_;
        const float* lf2_w  = ff2_w + (size_t)l * E_ * F_;
        const float* lf2_b  = ff2_b + (size_t)l * E_;
        const float* l2s    = ln2_s + (size_t)l * E_;
        const float* l2b    = ln2_b + (size_t)l * E_;

        tgemm<false><<<dim3(3 * E_ / 128, T_ / 128), 256, gemm_smem>>>(
            x, lqkv_w, lqkv_b, qkv, T_, 3 * E_, E_);
        attn_kernel<<<B_ * H_, 256, attn_smem>>>(qkv, attr_lens, attn);
        tgemm<false><<<dim3(E_ / 128, T_ / 128), 256, gemm_smem>>>(
            attn, lao_w, lao_b, tmp, T_, E_, E_);
        add_ln_kernel<<<T_ / 8, 256>>>(x, tmp, l1s, l1b, x);
        tgemm<true><<<dim3(F_ / 128, T_ / 128), 256, gemm_smem>>>(
            x, lf1_w, lf1_b, ff, T_, F_, E_);
        tgemm<false><<<dim3(E_ / 128, T_ / 128), 256, gemm_smem>>>(
            ff, lf2_w, lf2_b, tmp, T_, E_, F_);
        add_ln_kernel<<<T_ / 8, 256>>>(x, tmp, l2s, l2b, x);
    }

    pool_kernel<<<B_, 256>>>(x, attr_tf, attr_lens, attr_lens_user,
                             attr_feat, fw_W, fw_b,
                             user_ids, item_ids, user_emb, item_emb, outv);

    logits_kernel<<<B_, 512>>>(
        outv, out_emb, pos_targets, pos_lens, neg_targets, neg_lens,
        (float*)d_out);
}